// round 14
// baseline (speedup 1.0000x reference)
#include <cuda_runtime.h>
#include <cstdint>

#define NNODES 100000
#define NEDGES 600000
#define EPS 1e-5f
#define SLOPE 0.01f

// ---------------- scratch (device globals; no allocations allowed) ----------------
__device__ float g_Ta[(size_t)NNODES * 512];    // Horner workspace A
__device__ float g_Tb[(size_t)NNODES * 512];    // Horner workspace B
__device__ float g_stats3[3 * 512];             // per-layer: sum|sumsq|scale|shift
__device__ unsigned char g_zero[(size_t)NNODES * 12];  // deg | cnt | cur
__device__ int   g_rowptr[NNODES + 1];
__device__ int   g_bsum[128];
__device__ int   g_boff[128];
__device__ int   g_esrc[NEDGES];
__device__ float g_ew[NEDGES];

// ---------------- graph preprocessing ----------------
__global__ void deg_hist_kernel(const int* __restrict__ dst,
                                const float* __restrict__ ea,
                                float* __restrict__ deg, int* __restrict__ cnt, int E) {
    int e = blockIdx.x * blockDim.x + threadIdx.x;
    if (e < E) {
        int d = dst[e];
        atomicAdd(&deg[d], ea[e]);
        atomicAdd(&cnt[d], 1);
    }
}

__global__ void deg_to_dis_kernel(float* __restrict__ deg, int n) {
    int i = blockIdx.x * blockDim.x + threadIdx.x;
    if (i < n) {
        float d = deg[i];
        deg[i] = d > 0.0f ? rsqrtf(fmaxf(d, 1e-12f)) : 0.0f;
    }
}

// ---------------- CSR build ----------------
__global__ void scan1_kernel(const int* __restrict__ cnt, int* __restrict__ rowptr,
                             int* __restrict__ bsum) {
    __shared__ int s[1024];
    int t = threadIdx.x;
    int i = blockIdx.x * 1024 + t;
    int v = (i < NNODES) ? cnt[i] : 0;
    s[t] = v;
    __syncthreads();
#pragma unroll
    for (int off = 1; off < 1024; off <<= 1) {
        int add = (t >= off) ? s[t - off] : 0;
        __syncthreads();
        s[t] += add;
        __syncthreads();
    }
    if (i <= NNODES) rowptr[i] = s[t] - v;   // exclusive
    if (t == 1023) bsum[blockIdx.x] = s[1023];
}

__global__ void scan2_kernel(const int* __restrict__ bsum, int* __restrict__ boff, int nb) {
    if (threadIdx.x == 0) {
        int run = 0;
        for (int b = 0; b < nb; b++) { boff[b] = run; run += bsum[b]; }
    }
}

__global__ void scan3_kernel(int* __restrict__ rowptr, const int* __restrict__ boff) {
    int i = blockIdx.x * blockDim.x + threadIdx.x;
    if (i <= NNODES) rowptr[i] += boff[i >> 10];
}

// scatter with fused gcn_norm: ew = dis[src] * ea * dis[dst]
__global__ void scatter_kernel(const int* __restrict__ src, const int* __restrict__ dst,
                               const float* __restrict__ ea, const float* __restrict__ dis,
                               const int* __restrict__ rowptr, int* __restrict__ cur,
                               int* __restrict__ esrc, float* __restrict__ ew, int E) {
    int e = blockIdx.x * blockDim.x + threadIdx.x;
    if (e >= E) return;
    int s = src[e];
    int d = dst[e];
    int pos = rowptr[d] + atomicAdd(&cur[d], 1);
    esrc[pos] = s;
    ew[pos] = dis[s] * ea[e] * dis[d];
}

// ---------------- tf32 tensor-core GEMM (R10 winner config, untouched) ----------
__device__ __forceinline__ uint32_t f2tf32(float f) {
    uint32_t r;
    asm("cvt.rna.tf32.f32 %0, %1;" : "=r"(r) : "f"(f));
    return r;
}

__device__ __forceinline__ void mma_tf32(float* c, const uint32_t* a, const uint32_t* b) {
    asm volatile(
        "mma.sync.aligned.m16n8k8.row.col.f32.tf32.tf32.f32 "
        "{%0,%1,%2,%3}, {%4,%5,%6,%7}, {%8,%9}, {%0,%1,%2,%3};"
        : "+f"(c[0]), "+f"(c[1]), "+f"(c[2]), "+f"(c[3])
        : "r"(a[0]), "r"(a[1]), "r"(a[2]), "r"(a[3]), "r"(b[0]), "r"(b[1]));
}

__device__ __forceinline__ float bn_lrelu(float v, float sc, float sh) {
    float t = fmaf(v, sc, sh);
    return fmaxf(t, SLOPE * t);
}

template <int BN>
__global__ void __launch_bounds__(256)
gemm_tc_kernel(const float* __restrict__ A, int lda, const float* __restrict__ W,
               float* __restrict__ C, const float* __restrict__ bias,
               const float* __restrict__ bnStats, int M) {
    const int Fin = 128;
    constexpr int ASTR = 20;
    constexpr int BSTR = BN + 8;
    constexpr int NT = BN / 16;
    constexpr int PER = 16 * BN / 256;
    __shared__ uint32_t As[128 * ASTR];
    __shared__ uint32_t Bs[16 * BSTR];
    __shared__ float ScSh[256];

    const int tid = threadIdx.x;
    const int lane = tid & 31;
    const int wid = tid >> 5;
    const int k = blockIdx.x;
    const int rowBase = blockIdx.y * 128;
    const float* B = W + (size_t)k * Fin * BN;
    const int ldc = 4 * BN;

    const int wm = (wid & 3) * 32;
    const int wn = (wid >> 2) * (BN / 2);

    if (bnStats) {
        if (tid < 128) ScSh[tid] = bnStats[256 + tid];
        else ScSh[tid] = bnStats[384 + tid - 128];
    }

    float acc[2][NT][4];
#pragma unroll
    for (int i = 0; i < 2; i++)
#pragma unroll
        for (int j = 0; j < NT; j++)
#pragma unroll
            for (int t = 0; t < 4; t++) acc[i][j][t] = 0.f;

    const int arow = tid >> 1;
    const int acol = (tid & 1) * 8;
    const int gr = rowBase + arow;
    const int bj0 = tid * PER;
    const int bkr = bj0 / BN;
    const int bnc = bj0 % BN;
    if (bnStats) __syncthreads();

    float va[8];
    float vb[PER];

    auto load_regs = [&](int k0) {
#pragma unroll
        for (int j = 0; j < 8; j++) va[j] = 0.f;
        if (gr < M) {
            const float* ap = A + (size_t)gr * lda + k0 + acol;
            *reinterpret_cast<float4*>(&va[0]) = *reinterpret_cast<const float4*>(ap);
            *reinterpret_cast<float4*>(&va[4]) = *reinterpret_cast<const float4*>(ap + 4);
            if (bnStats) {
                int cb = k0 + acol;
#pragma unroll
                for (int j = 0; j < 8; j++)
                    va[j] = bn_lrelu(va[j], ScSh[cb + j], ScSh[128 + cb + j]);
            }
        }
        const float* bp = B + (size_t)k0 * BN + bj0;
#pragma unroll
        for (int j = 0; j < PER; j += 4)
            *reinterpret_cast<float4*>(&vb[j]) = *reinterpret_cast<const float4*>(bp + j);
    };

    auto store_smem = [&]() {
        uint32_t* as = &As[arow * ASTR + acol];
#pragma unroll
        for (int j = 0; j < 8; j++) as[j] = f2tf32(va[j]);
        uint32_t* bs = &Bs[bkr * BSTR + bnc];
#pragma unroll
        for (int j = 0; j < PER; j++) bs[j] = f2tf32(vb[j]);
    };

    load_regs(0);
    store_smem();
    __syncthreads();

#pragma unroll
    for (int it = 0; it < Fin / 16; it++) {
        if (it < Fin / 16 - 1) load_regs((it + 1) * 16);

#pragma unroll
        for (int ko = 0; ko < 16; ko += 8) {
            uint32_t af[2][4];
#pragma unroll
            for (int mt = 0; mt < 2; mt++) {
                int mrow = wm + mt * 16 + (lane >> 2);
                int kcol = ko + (lane & 3);
                af[mt][0] = As[mrow * ASTR + kcol];
                af[mt][1] = As[(mrow + 8) * ASTR + kcol];
                af[mt][2] = As[mrow * ASTR + kcol + 4];
                af[mt][3] = As[(mrow + 8) * ASTR + kcol + 4];
            }
            uint32_t bf[NT][2];
#pragma unroll
            for (int nt = 0; nt < NT; nt++) {
                int ncol = wn + nt * 8 + (lane >> 2);
                int krow = ko + (lane & 3);
                bf[nt][0] = Bs[krow * BSTR + ncol];
                bf[nt][1] = Bs[(krow + 4) * BSTR + ncol];
            }
#pragma unroll
            for (int mt = 0; mt < 2; mt++)
#pragma unroll
                for (int nt = 0; nt < NT; nt++)
                    mma_tf32(acc[mt][nt], af[mt], bf[nt]);
        }
        __syncthreads();
        if (it < Fin / 16 - 1) {
            store_smem();
            __syncthreads();
        }
    }

#pragma unroll
    for (int mt = 0; mt < 2; mt++) {
        int r0 = rowBase + wm + mt * 16 + (lane >> 2);
#pragma unroll
        for (int nt = 0; nt < NT; nt++) {
            int ncol = wn + nt * 8 + (lane & 3) * 2;
            float bx = 0.f, by = 0.f;
            if (BN == 128 && k == 0 && bias) {
                bx = bias[ncol]; by = bias[ncol + 1];
            }
            int gc = k * BN + ncol;
            if (r0 < M) {
                float2 o = make_float2(acc[mt][nt][0] + bx, acc[mt][nt][1] + by);
                *reinterpret_cast<float2*>(C + (size_t)r0 * ldc + gc) = o;
            }
            if (r0 + 8 < M) {
                float2 o = make_float2(acc[mt][nt][2] + bx, acc[mt][nt][3] + by);
                *reinterpret_cast<float2*>(C + (size_t)(r0 + 8) * ldc + gc) = o;
            }
        }
    }
}

// ---------------- CSR-gather SpMM; optional fused BN-stats on final hop ----------
// LANES=32 -> F=128, 8 nodes/block; LANES=16 -> F=64, 16 nodes/block.
// Grids divide exactly (100000*LANES % 256 == 0): no partial blocks.
template <int LANES, bool STATS>
__global__ void spmm_csr_kernel(const int* __restrict__ rowptr,
                                const int* __restrict__ esrc,
                                const float* __restrict__ ew,
                                const float* __restrict__ in,
                                float* __restrict__ out, int ld,
                                float* __restrict__ stats) {
    constexpr int F = LANES * 4;
    __shared__ float ssum[STATS ? F : 1];
    __shared__ float ssq[STATS ? F : 1];
    int tid = threadIdx.x;
    if (STATS) {
        for (int i = tid; i < F; i += 256) { ssum[i] = 0.f; ssq[i] = 0.f; }
        __syncthreads();
    }
    int idx = blockIdx.x * blockDim.x + tid;
    int node = idx / LANES;
    int lane = idx % LANES;
    int e0 = rowptr[node];
    int e1 = rowptr[node + 1];
    int c = lane * 4;
    float4 acc = make_float4(0.f, 0.f, 0.f, 0.f);
    int e = e0;
    for (; e + 2 <= e1; e += 2) {
        int s0 = __ldg(&esrc[e]);
        int s1 = __ldg(&esrc[e + 1]);
        float w0 = __ldg(&ew[e]);
        float w1 = __ldg(&ew[e + 1]);
        float4 v0 = *reinterpret_cast<const float4*>(in + (size_t)s0 * ld + c);
        float4 v1 = *reinterpret_cast<const float4*>(in + (size_t)s1 * ld + c);
        acc.x += w0 * v0.x + w1 * v1.x;
        acc.y += w0 * v0.y + w1 * v1.y;
        acc.z += w0 * v0.z + w1 * v1.z;
        acc.w += w0 * v0.w + w1 * v1.w;
    }
    if (e < e1) {
        int s = __ldg(&esrc[e]);
        float w = __ldg(&ew[e]);
        float4 v = *reinterpret_cast<const float4*>(in + (size_t)s * ld + c);
        acc.x += w * v.x; acc.y += w * v.y;
        acc.z += w * v.z; acc.w += w * v.w;
    }
    float4* o = reinterpret_cast<float4*>(out + (size_t)node * ld + c);
    float4 cur = *o;
    cur.x += acc.x; cur.y += acc.y; cur.z += acc.z; cur.w += acc.w;
    *o = cur;
    if (STATS) {
        atomicAdd(&ssum[c + 0], cur.x); atomicAdd(&ssq[c + 0], cur.x * cur.x);
        atomicAdd(&ssum[c + 1], cur.y); atomicAdd(&ssq[c + 1], cur.y * cur.y);
        atomicAdd(&ssum[c + 2], cur.z); atomicAdd(&ssq[c + 2], cur.z * cur.z);
        atomicAdd(&ssum[c + 3], cur.w); atomicAdd(&ssq[c + 3], cur.w * cur.w);
        __syncthreads();
        for (int i = tid; i < F; i += 256) {
            atomicAdd(&stats[i], ssum[i]);
            atomicAdd(&stats[128 + i], ssq[i]);
        }
    }
}

// ---------------- BatchNorm finalize + final apply ----------------
__global__ void bn_finalize_kernel(const float* __restrict__ g,
                                   const float* __restrict__ be,
                                   float* __restrict__ stats, int F, float invN) {
    int c = threadIdx.x;
    if (c < F) {
        float m = stats[c] * invN;
        float v = stats[128 + c] * invN - m * m;
        float sc = g[c] * rsqrtf(v + EPS);
        stats[256 + c] = sc;
        stats[384 + c] = be[c] - m * sc;
    }
}

__global__ void bn_apply_kernel(const float* __restrict__ in, int ldi,
                                float* __restrict__ out, int ldo,
                                const float* __restrict__ stats,
                                int logF, long long total) {
    long long i = (long long)blockIdx.x * blockDim.x + threadIdx.x;
    if (i >= total) return;
    int F1 = (1 << logF) - 1;
    int r = (int)(i >> logF);
    int c = (int)(i & F1);
    float v = in[(size_t)r * ldi + c] * stats[256 + c] + stats[384 + c];
    out[(size_t)r * ldo + c] = v > 0.f ? v : SLOPE * v;
}

// ---------------- host ----------------
static void run_spmm_chain(int Fout, float* T,
                           const int* rowptr, const int* esrc, const float* ew,
                           float* statsL) {
    const int LD = 4 * Fout;
    if (Fout == 128) {
        const int blocks = NNODES * 32 / 256;
        spmm_csr_kernel<32, false><<<blocks, 256>>>(rowptr, esrc, ew,
                                                    T + 3 * 128, T + 2 * 128, LD, nullptr);
        spmm_csr_kernel<32, false><<<blocks, 256>>>(rowptr, esrc, ew,
                                                    T + 2 * 128, T + 1 * 128, LD, nullptr);
        spmm_csr_kernel<32, true><<<blocks, 256>>>(rowptr, esrc, ew,
                                                   T + 1 * 128, T, LD, statsL);
    } else {
        const int blocks = NNODES * 16 / 256;
        spmm_csr_kernel<16, false><<<blocks, 256>>>(rowptr, esrc, ew,
                                                    T + 3 * 64, T + 2 * 64, LD, nullptr);
        spmm_csr_kernel<16, false><<<blocks, 256>>>(rowptr, esrc, ew,
                                                    T + 2 * 64, T + 1 * 64, LD, nullptr);
        spmm_csr_kernel<16, true><<<blocks, 256>>>(rowptr, esrc, ew,
                                                   T + 1 * 64, T, LD, statsL);
    }
}

extern "C" void kernel_launch(void* const* d_in, const int* in_sizes, int n_in,
                              void* d_out, int out_size) {
    const float* y   = (const float*)d_in[0];
    const int*   ei  = (const int*)d_in[1];
    const float* ea  = (const float*)d_in[2];
    const float* W1  = (const float*)d_in[3];
    const float* b1  = (const float*)d_in[4];
    const float* g1  = (const float*)d_in[5];
    const float* be1 = (const float*)d_in[6];
    const float* W2  = (const float*)d_in[7];
    const float* b2  = (const float*)d_in[8];
    const float* g2  = (const float*)d_in[9];
    const float* be2 = (const float*)d_in[10];
    const float* W3  = (const float*)d_in[11];
    const float* g3  = (const float*)d_in[12];
    const float* be3 = (const float*)d_in[13];

    // one-time host resources
    static cudaStream_t sB = nullptr;
    static cudaEvent_t evFork = nullptr, evPrep = nullptr;
    if (!sB) {
        cudaStreamCreateWithFlags(&sB, cudaStreamNonBlocking);
        cudaEventCreateWithFlags(&evFork, cudaEventDisableTiming);
        cudaEventCreateWithFlags(&evPrep, cudaEventDisableTiming);
    }

    float *Ta, *Tb, *stats3, *ew;
    unsigned char* zero;
    int *rowptr, *bsum, *boff, *esrc;
    cudaGetSymbolAddress((void**)&Ta, g_Ta);
    cudaGetSymbolAddress((void**)&Tb, g_Tb);
    cudaGetSymbolAddress((void**)&stats3, g_stats3);
    cudaGetSymbolAddress((void**)&zero, g_zero);
    cudaGetSymbolAddress((void**)&rowptr, g_rowptr);
    cudaGetSymbolAddress((void**)&bsum, g_bsum);
    cudaGetSymbolAddress((void**)&boff, g_boff);
    cudaGetSymbolAddress((void**)&esrc, g_esrc);
    cudaGetSymbolAddress((void**)&ew, g_ew);

    float* deg = (float*)zero;
    int*   cnt = (int*)(zero + 4 * (size_t)NNODES);
    int*   cur = (int*)(zero + 8 * (size_t)NNODES);

    const int* src = ei;
    const int* dst = ei + NEDGES;
    const int EB = (NEDGES + 255) / 256;
    const int NB = (NNODES + 255) / 256;
    const int SCAN_BLOCKS = (NNODES + 1 + 1023) / 1024;
    const int MT = (NNODES + 127) / 128;
    dim3 ggrid(4, MT);

    // zero all three stats buffers (sum/sumsq halves) up front
    cudaMemsetAsync(stats3, 0, 3 * 512 * sizeof(float), 0);

    // fork prep chain onto sB (capture-legal: event from captured stream first)
    cudaEventRecord(evFork, 0);
    cudaStreamWaitEvent(sB, evFork, 0);
    cudaMemsetAsync(zero, 0, (size_t)NNODES * 12, sB);
    deg_hist_kernel<<<EB, 256, 0, sB>>>(dst, ea, deg, cnt, NEDGES);
    deg_to_dis_kernel<<<NB, 256, 0, sB>>>(deg, NNODES);
    scan1_kernel<<<SCAN_BLOCKS, 1024, 0, sB>>>(cnt, rowptr, bsum);
    scan2_kernel<<<1, 32, 0, sB>>>(bsum, boff, SCAN_BLOCKS);
    scan3_kernel<<<(NNODES + 1 + 255) / 256, 256, 0, sB>>>(rowptr, boff);
    scatter_kernel<<<EB, 256, 0, sB>>>(src, dst, ea, deg, rowptr, cur, esrc, ew, NEDGES);
    cudaEventRecord(evPrep, sB);

    // layer-1 GEMM on s0 overlaps the whole prep chain
    gemm_tc_kernel<128><<<ggrid, 256>>>(y, 128, W1, Ta, b1, nullptr, NNODES);
    cudaStreamWaitEvent(0, evPrep, 0);

    // layer 1: hops (+stats fused into last hop)
    run_spmm_chain(128, Ta, rowptr, esrc, ew, stats3);
    bn_finalize_kernel<<<1, 128>>>(g1, be1, stats3, 128, 1.0f / NNODES);

    // layer 2
    gemm_tc_kernel<128><<<ggrid, 256>>>(Ta, 512, W2, Tb, b2, stats3, NNODES);
    run_spmm_chain(128, Tb, rowptr, esrc, ew, stats3 + 512);
    bn_finalize_kernel<<<1, 128>>>(g2, be2, stats3 + 512, 128, 1.0f / NNODES);

    // layer 3
    gemm_tc_kernel<64><<<ggrid, 256>>>(Tb, 512, W3, Ta, nullptr, stats3 + 512, NNODES);
    run_spmm_chain(64, Ta, rowptr, esrc, ew, stats3 + 1024);
    bn_finalize_kernel<<<1, 128>>>(g3, be3, stats3 + 1024, 64, 1.0f / NNODES);
    {
        long long total = (long long)NNODES * 64;
        bn_apply_kernel<<<(unsigned)((total + 255) / 256), 256>>>(Ta, 256, (float*)d_out, 64,
                                                                  stats3 + 1024, 6, total);
    }
}

// round 15
// speedup vs baseline: 1.2335x; 1.2335x over previous
#include <cuda_runtime.h>
#include <cstdint>

#define NNODES 100000
#define NEDGES 600000
#define EPS 1e-5f
#define SLOPE 0.01f

// ---------------- scratch (device globals; no allocations allowed) ----------------
__device__ float g_Ta[(size_t)NNODES * 512];    // Horner workspace A
__device__ float g_Tb[(size_t)NNODES * 512];    // Horner workspace B
__device__ float g_stats[512];                  // sum | sumsq | scale | shift
__device__ unsigned char g_zero[(size_t)NNODES * 12];  // deg | cnt | cur
__device__ int   g_rowptr[NNODES + 1];
__device__ int   g_bsum[128];
__device__ int   g_boff[128];
__device__ int   g_esrc[NEDGES];
__device__ float g_ew[NEDGES];

// ---------------- graph preprocessing ----------------
__global__ void deg_hist_kernel(const int* __restrict__ dst,
                                const float* __restrict__ ea,
                                float* __restrict__ deg, int* __restrict__ cnt, int E) {
    int e = blockIdx.x * blockDim.x + threadIdx.x;
    if (e < E) {
        int d = dst[e];
        atomicAdd(&deg[d], ea[e]);
        atomicAdd(&cnt[d], 1);
    }
}

__global__ void deg_to_dis_kernel(float* __restrict__ deg, int n) {
    int i = blockIdx.x * blockDim.x + threadIdx.x;
    if (i < n) {
        float d = deg[i];
        deg[i] = d > 0.0f ? rsqrtf(fmaxf(d, 1e-12f)) : 0.0f;
    }
}

// ---------------- CSR build ----------------
__global__ void scan1_kernel(const int* __restrict__ cnt, int* __restrict__ rowptr,
                             int* __restrict__ bsum) {
    __shared__ int s[1024];
    int t = threadIdx.x;
    int i = blockIdx.x * 1024 + t;
    int v = (i < NNODES) ? cnt[i] : 0;
    s[t] = v;
    __syncthreads();
#pragma unroll
    for (int off = 1; off < 1024; off <<= 1) {
        int add = (t >= off) ? s[t - off] : 0;
        __syncthreads();
        s[t] += add;
        __syncthreads();
    }
    if (i <= NNODES) rowptr[i] = s[t] - v;   // exclusive
    if (t == 1023) bsum[blockIdx.x] = s[1023];
}

__global__ void scan2_kernel(const int* __restrict__ bsum, int* __restrict__ boff, int nb) {
    if (threadIdx.x == 0) {
        int run = 0;
        for (int b = 0; b < nb; b++) { boff[b] = run; run += bsum[b]; }
    }
}

__global__ void scan3_kernel(int* __restrict__ rowptr, const int* __restrict__ boff) {
    int i = blockIdx.x * blockDim.x + threadIdx.x;
    if (i <= NNODES) rowptr[i] += boff[i >> 10];
}

// scatter with fused gcn_norm: ew = dis[src] * ea * dis[dst]
__global__ void scatter_kernel(const int* __restrict__ src, const int* __restrict__ dst,
                               const float* __restrict__ ea, const float* __restrict__ dis,
                               const int* __restrict__ rowptr, int* __restrict__ cur,
                               int* __restrict__ esrc, float* __restrict__ ew, int E) {
    int e = blockIdx.x * blockDim.x + threadIdx.x;
    if (e >= E) return;
    int s = src[e];
    int d = dst[e];
    int pos = rowptr[d] + atomicAdd(&cur[d], 1);
    esrc[pos] = s;
    ew[pos] = dis[s] * ea[e] * dis[d];
}

// ---------------- tf32 tensor-core GEMM (R10 winner config, untouched) ----------
__device__ __forceinline__ uint32_t f2tf32(float f) {
    uint32_t r;
    asm("cvt.rna.tf32.f32 %0, %1;" : "=r"(r) : "f"(f));
    return r;
}

__device__ __forceinline__ void mma_tf32(float* c, const uint32_t* a, const uint32_t* b) {
    asm volatile(
        "mma.sync.aligned.m16n8k8.row.col.f32.tf32.tf32.f32 "
        "{%0,%1,%2,%3}, {%4,%5,%6,%7}, {%8,%9}, {%0,%1,%2,%3};"
        : "+f"(c[0]), "+f"(c[1]), "+f"(c[2]), "+f"(c[3])
        : "r"(a[0]), "r"(a[1]), "r"(a[2]), "r"(a[3]), "r"(b[0]), "r"(b[1]));
}

__device__ __forceinline__ float bn_lrelu(float v, float sc, float sh) {
    float t = fmaf(v, sc, sh);
    return fmaxf(t, SLOPE * t);
}

template <int BN>
__global__ void __launch_bounds__(256)
gemm_tc_kernel(const float* __restrict__ A, int lda, const float* __restrict__ W,
               float* __restrict__ C, const float* __restrict__ bias,
               const float* __restrict__ bnStats, int M) {
    const int Fin = 128;
    constexpr int ASTR = 20;
    constexpr int BSTR = BN + 8;
    constexpr int NT = BN / 16;
    constexpr int PER = 16 * BN / 256;
    __shared__ uint32_t As[128 * ASTR];
    __shared__ uint32_t Bs[16 * BSTR];
    __shared__ float ScSh[256];

    const int tid = threadIdx.x;
    const int lane = tid & 31;
    const int wid = tid >> 5;
    const int k = blockIdx.x;
    const int rowBase = blockIdx.y * 128;
    const float* B = W + (size_t)k * Fin * BN;
    const int ldc = 4 * BN;

    const int wm = (wid & 3) * 32;
    const int wn = (wid >> 2) * (BN / 2);

    if (bnStats) {
        if (tid < 128) ScSh[tid] = bnStats[256 + tid];
        else ScSh[tid] = bnStats[384 + tid - 128];
    }

    float acc[2][NT][4];
#pragma unroll
    for (int i = 0; i < 2; i++)
#pragma unroll
        for (int j = 0; j < NT; j++)
#pragma unroll
            for (int t = 0; t < 4; t++) acc[i][j][t] = 0.f;

    const int arow = tid >> 1;
    const int acol = (tid & 1) * 8;
    const int gr = rowBase + arow;
    const int bj0 = tid * PER;
    const int bkr = bj0 / BN;
    const int bnc = bj0 % BN;
    if (bnStats) __syncthreads();

    float va[8];
    float vb[PER];

    auto load_regs = [&](int k0) {
#pragma unroll
        for (int j = 0; j < 8; j++) va[j] = 0.f;
        if (gr < M) {
            const float* ap = A + (size_t)gr * lda + k0 + acol;
            *reinterpret_cast<float4*>(&va[0]) = *reinterpret_cast<const float4*>(ap);
            *reinterpret_cast<float4*>(&va[4]) = *reinterpret_cast<const float4*>(ap + 4);
            if (bnStats) {
                int cb = k0 + acol;
#pragma unroll
                for (int j = 0; j < 8; j++)
                    va[j] = bn_lrelu(va[j], ScSh[cb + j], ScSh[128 + cb + j]);
            }
        }
        const float* bp = B + (size_t)k0 * BN + bj0;
#pragma unroll
        for (int j = 0; j < PER; j += 4)
            *reinterpret_cast<float4*>(&vb[j]) = *reinterpret_cast<const float4*>(bp + j);
    };

    auto store_smem = [&]() {
        uint32_t* as = &As[arow * ASTR + acol];
#pragma unroll
        for (int j = 0; j < 8; j++) as[j] = f2tf32(va[j]);
        uint32_t* bs = &Bs[bkr * BSTR + bnc];
#pragma unroll
        for (int j = 0; j < PER; j++) bs[j] = f2tf32(vb[j]);
    };

    load_regs(0);
    store_smem();
    __syncthreads();

#pragma unroll
    for (int it = 0; it < Fin / 16; it++) {
        if (it < Fin / 16 - 1) load_regs((it + 1) * 16);

#pragma unroll
        for (int ko = 0; ko < 16; ko += 8) {
            uint32_t af[2][4];
#pragma unroll
            for (int mt = 0; mt < 2; mt++) {
                int mrow = wm + mt * 16 + (lane >> 2);
                int kcol = ko + (lane & 3);
                af[mt][0] = As[mrow * ASTR + kcol];
                af[mt][1] = As[(mrow + 8) * ASTR + kcol];
                af[mt][2] = As[mrow * ASTR + kcol + 4];
                af[mt][3] = As[(mrow + 8) * ASTR + kcol + 4];
            }
            uint32_t bf[NT][2];
#pragma unroll
            for (int nt = 0; nt < NT; nt++) {
                int ncol = wn + nt * 8 + (lane >> 2);
                int krow = ko + (lane & 3);
                bf[nt][0] = Bs[krow * BSTR + ncol];
                bf[nt][1] = Bs[(krow + 4) * BSTR + ncol];
            }
#pragma unroll
            for (int mt = 0; mt < 2; mt++)
#pragma unroll
                for (int nt = 0; nt < NT; nt++)
                    mma_tf32(acc[mt][nt], af[mt], bf[nt]);
        }
        __syncthreads();
        if (it < Fin / 16 - 1) {
            store_smem();
            __syncthreads();
        }
    }

#pragma unroll
    for (int mt = 0; mt < 2; mt++) {
        int r0 = rowBase + wm + mt * 16 + (lane >> 2);
#pragma unroll
        for (int nt = 0; nt < NT; nt++) {
            int ncol = wn + nt * 8 + (lane & 3) * 2;
            float bx = 0.f, by = 0.f;
            if (BN == 128 && k == 0 && bias) {
                bx = bias[ncol]; by = bias[ncol + 1];
            }
            int gc = k * BN + ncol;
            if (r0 < M) {
                float2 o = make_float2(acc[mt][nt][0] + bx, acc[mt][nt][1] + by);
                *reinterpret_cast<float2*>(C + (size_t)r0 * ldc + gc) = o;
            }
            if (r0 + 8 < M) {
                float2 o = make_float2(acc[mt][nt][2] + bx, acc[mt][nt][3] + by);
                *reinterpret_cast<float2*>(C + (size_t)(r0 + 8) * ldc + gc) = o;
            }
        }
    }
}

// ---------------- CSR-gather SpMM: out[d] += sum_e w_e * in[src_e] ----------------
template <int LANES>
__global__ void spmm_csr_kernel(const int* __restrict__ rowptr,
                                const int* __restrict__ esrc,
                                const float* __restrict__ ew,
                                const float* __restrict__ in,
                                float* __restrict__ out, int ld) {
    int idx = blockIdx.x * blockDim.x + threadIdx.x;
    int node = idx / LANES;
    int lane = idx % LANES;
    if (node >= NNODES) return;
    int e0 = rowptr[node];
    int e1 = rowptr[node + 1];
    int c = lane * 4;
    float4 acc = make_float4(0.f, 0.f, 0.f, 0.f);
    int e = e0;
    for (; e + 2 <= e1; e += 2) {
        int s0 = __ldg(&esrc[e]);
        int s1 = __ldg(&esrc[e + 1]);
        float w0 = __ldg(&ew[e]);
        float w1 = __ldg(&ew[e + 1]);
        float4 v0 = *reinterpret_cast<const float4*>(in + (size_t)s0 * ld + c);
        float4 v1 = *reinterpret_cast<const float4*>(in + (size_t)s1 * ld + c);
        acc.x += w0 * v0.x + w1 * v1.x;
        acc.y += w0 * v0.y + w1 * v1.y;
        acc.z += w0 * v0.z + w1 * v1.z;
        acc.w += w0 * v0.w + w1 * v1.w;
    }
    if (e < e1) {
        int s = __ldg(&esrc[e]);
        float w = __ldg(&ew[e]);
        float4 v = *reinterpret_cast<const float4*>(in + (size_t)s * ld + c);
        acc.x += w * v.x; acc.y += w * v.y;
        acc.z += w * v.z; acc.w += w * v.w;
    }
    float4* o = reinterpret_cast<float4*>(out + (size_t)node * ld + c);
    float4 cur = *o;
    cur.x += acc.x; cur.y += acc.y; cur.z += acc.z; cur.w += acc.w;
    *o = cur;
}

// ---------------- BatchNorm ----------------
__global__ void bn_stats_kernel(const float* __restrict__ x, int ld, int n,
                                float* __restrict__ stats) {
    int col = threadIdx.x;
    int r0 = blockIdx.x * 128;
    int rend = min(r0 + 128, n);
    float s = 0.f, ss = 0.f;
    for (int r = r0; r < rend; r++) {
        float v = x[(size_t)r * ld + col];
        s += v;
        ss += v * v;
    }
    atomicAdd(&stats[col], s);
    atomicAdd(&stats[128 + col], ss);
}

__global__ void bn_finalize_kernel(const float* __restrict__ g,
                                   const float* __restrict__ be,
                                   float* __restrict__ stats, int F, float invN) {
    int c = threadIdx.x;
    if (c < F) {
        float m = stats[c] * invN;
        float v = stats[128 + c] * invN - m * m;
        float sc = g[c] * rsqrtf(v + EPS);
        stats[256 + c] = sc;
        stats[384 + c] = be[c] - m * sc;
    }
}

__global__ void bn_apply_kernel(const float* __restrict__ in, int ldi,
                                float* __restrict__ out, int ldo,
                                const float* __restrict__ stats,
                                int logF, long long total) {
    long long i = (long long)blockIdx.x * blockDim.x + threadIdx.x;
    if (i >= total) return;
    int F1 = (1 << logF) - 1;
    int r = (int)(i >> logF);
    int c = (int)(i & F1);
    float v = in[(size_t)r * ldi + c] * stats[256 + c] + stats[384 + c];
    out[(size_t)r * ldo + c] = v > 0.f ? v : SLOPE * v;
}

// ---------------- host helpers ----------------
static void run_spmm_chain(int Fout, float* T,
                           const int* rowptr, const int* esrc, const float* ew) {
    const int LD = 4 * Fout;
    for (int k = 2; k >= 0; k--) {
        if (Fout == 128) {
            int blocks = (NNODES * 32 + 255) / 256;
            spmm_csr_kernel<32><<<blocks, 256>>>(rowptr, esrc, ew,
                                                 T + (size_t)(k + 1) * Fout,
                                                 T + (size_t)k * Fout, LD);
        } else {
            int blocks = (NNODES * 16 + 255) / 256;
            spmm_csr_kernel<16><<<blocks, 256>>>(rowptr, esrc, ew,
                                                 T + (size_t)(k + 1) * Fout,
                                                 T + (size_t)k * Fout, LD);
        }
    }
}

static void run_bn_stats(const float* T, int Fout,
                         const float* gamma, const float* beta, float* stats) {
    const int LD = 4 * Fout;
    cudaMemsetAsync(stats, 0, 256 * sizeof(float), 0);
    bn_stats_kernel<<<(NNODES + 127) / 128, Fout>>>(T, LD, NNODES, stats);
    bn_finalize_kernel<<<1, 128>>>(gamma, beta, stats, Fout, 1.0f / NNODES);
}

extern "C" void kernel_launch(void* const* d_in, const int* in_sizes, int n_in,
                              void* d_out, int out_size) {
    const float* y   = (const float*)d_in[0];
    const int*   ei  = (const int*)d_in[1];
    const float* ea  = (const float*)d_in[2];
    const float* W1  = (const float*)d_in[3];
    const float* b1  = (const float*)d_in[4];
    const float* g1  = (const float*)d_in[5];
    const float* be1 = (const float*)d_in[6];
    const float* W2  = (const float*)d_in[7];
    const float* b2  = (const float*)d_in[8];
    const float* g2  = (const float*)d_in[9];
    const float* be2 = (const float*)d_in[10];
    const float* W3  = (const float*)d_in[11];
    const float* g3  = (const float*)d_in[12];
    const float* be3 = (const float*)d_in[13];

    // one-time host resources
    static cudaStream_t sB = nullptr;
    static cudaEvent_t evFork = nullptr, evPrep = nullptr;
    if (!sB) {
        cudaStreamCreateWithFlags(&sB, cudaStreamNonBlocking);
        cudaEventCreateWithFlags(&evFork, cudaEventDisableTiming);
        cudaEventCreateWithFlags(&evPrep, cudaEventDisableTiming);
    }

    float *Ta, *Tb, *stats, *ew;
    unsigned char* zero;
    int *rowptr, *bsum, *boff, *esrc;
    cudaGetSymbolAddress((void**)&Ta, g_Ta);
    cudaGetSymbolAddress((void**)&Tb, g_Tb);
    cudaGetSymbolAddress((void**)&stats, g_stats);
    cudaGetSymbolAddress((void**)&zero, g_zero);
    cudaGetSymbolAddress((void**)&rowptr, g_rowptr);
    cudaGetSymbolAddress((void**)&bsum, g_bsum);
    cudaGetSymbolAddress((void**)&boff, g_boff);
    cudaGetSymbolAddress((void**)&esrc, g_esrc);
    cudaGetSymbolAddress((void**)&ew, g_ew);

    float* deg = (float*)zero;
    int*   cnt = (int*)(zero + 4 * (size_t)NNODES);
    int*   cur = (int*)(zero + 8 * (size_t)NNODES);

    const int* src = ei;
    const int* dst = ei + NEDGES;
    const int EB = (NEDGES + 255) / 256;
    const int NB = (NNODES + 255) / 256;
    const int SCAN_BLOCKS = (NNODES + 1 + 1023) / 1024;
    dim3 ggrid(4, (NNODES + 127) / 128);

    // ---- fork: full prep chain on sB, hidden under layer-1 GEMM on s0 ----
    cudaEventRecord(evFork, 0);
    cudaStreamWaitEvent(sB, evFork, 0);
    cudaMemsetAsync(zero, 0, (size_t)NNODES * 12, sB);
    deg_hist_kernel<<<EB, 256, 0, sB>>>(dst, ea, deg, cnt, NEDGES);
    deg_to_dis_kernel<<<NB, 256, 0, sB>>>(deg, NNODES);
    scan1_kernel<<<SCAN_BLOCKS, 1024, 0, sB>>>(cnt, rowptr, bsum);
    scan2_kernel<<<1, 32, 0, sB>>>(bsum, boff, SCAN_BLOCKS);
    scan3_kernel<<<(NNODES + 1 + 255) / 256, 256, 0, sB>>>(rowptr, boff);
    scatter_kernel<<<EB, 256, 0, sB>>>(src, dst, ea, deg, rowptr, cur, esrc, ew, NEDGES);
    cudaEventRecord(evPrep, sB);

    // layer-1 GEMM on s0 (overlaps prep)
    gemm_tc_kernel<128><<<ggrid, 256>>>(y, 128, W1, Ta, b1, nullptr, NNODES);
    cudaStreamWaitEvent(0, evPrep, 0);

    // layer 1: hops + BN stats (apply fused into layer-2 GEMM)
    run_spmm_chain(128, Ta, rowptr, esrc, ew);
    run_bn_stats(Ta, 128, g1, be1, stats);

    // layer 2
    gemm_tc_kernel<128><<<ggrid, 256>>>(Ta, 512, W2, Tb, b2, stats, NNODES);
    run_spmm_chain(128, Tb, rowptr, esrc, ew);
    run_bn_stats(Tb, 128, g2, be2, stats);

    // layer 3
    gemm_tc_kernel<64><<<ggrid, 256>>>(Tb, 512, W3, Ta, nullptr, stats, NNODES);
    run_spmm_chain(64, Ta, rowptr, esrc, ew);
    run_bn_stats(Ta, 64, g3, be3, stats);
    {
        long long total = (long long)NNODES * 64;
        bn_apply_kernel<<<(unsigned)((total + 255) / 256), 256>>>(Ta, 256, (float*)d_out, 64,
                                                                  stats, 6, total);
    }
}